// round 4
// baseline (speedup 1.0000x reference)
#include <cuda_runtime.h>
#include <cuda_bf16.h>
#include <math.h>
#include <stdint.h>

#define B 4
#define T 128
#define NTOK 196
#define D 768
#define KF 16
#define KT 49
#define NF (B*KF)   // 64 selected frames

// ---- output layout (float32, concatenated flat) ----
#define Z_N       (B*KF*KT*D)
#define FIDX_OFF  ((size_t)Z_N)
#define TIDX_OFF  (FIDX_OFF + B*KF)
#define FMASK_OFF (TIDX_OFF + NF*KT)
#define TMASK_OFF (FMASK_OFF + B*T)
#define TOTAL_OUT (TMASK_OFF + (size_t)B*T*NTOK)

typedef unsigned long long ull;

// ---- device scratch ----
__device__ float g_frame_repr[B*T*D];
__device__ int   g_frame_idx[NF];
__device__ int   g_token_idx[NF*KT];
__device__ float g_GFp[24][B*128*128];
__device__ float g_G[(size_t)NF*NTOK*NTOK];

// ---- warp argmax: strict-greater wins, ties -> lowest index; broadcasts ----
__device__ __forceinline__ void warp_argmax(float& v, int& ix) {
#pragma unroll
    for (int o = 16; o; o >>= 1) {
        float ov = __shfl_down_sync(0xffffffffu, v, o);
        int   oi = __shfl_down_sync(0xffffffffu, ix, o);
        if (ov > v || (ov == v && oi < ix)) { v = ov; ix = oi; }
    }
    v  = __shfl_sync(0xffffffffu, v, 0);
    ix = __shfl_sync(0xffffffffu, ix, 0);
}

__device__ __forceinline__ uint32_t smem_u32(const void* p) {
    uint32_t a;
    asm("{ .reg .u64 t; cvta.to.shared.u64 t, %1; cvt.u32.u64 %0, t; }" : "=r"(a) : "l"(p));
    return a;
}
__device__ __forceinline__ void ldsm4(uint32_t* r, uint32_t addr) {
    asm volatile("ldmatrix.sync.aligned.m8n8.x4.shared.b16 {%0,%1,%2,%3}, [%4];"
        : "=r"(r[0]), "=r"(r[1]), "=r"(r[2]), "=r"(r[3]) : "r"(addr));
}
__device__ __forceinline__ void mma16816(float* d, const uint32_t* a,
                                         uint32_t b0, uint32_t b1) {
    asm volatile("mma.sync.aligned.m16n8k16.row.col.f32.bf16.bf16.f32 "
        "{%0,%1,%2,%3}, {%4,%5,%6,%7}, {%8,%9}, {%0,%1,%2,%3};"
        : "+f"(d[0]), "+f"(d[1]), "+f"(d[2]), "+f"(d[3])
        : "r"(a[0]), "r"(a[1]), "r"(a[2]), "r"(a[3]), "r"(b0), "r"(b1));
}

// ================= K1: masked-mean frame repr (+ zero fmask) =================
__global__ void frame_repr_kernel(const float* __restrict__ x,
                                  const float* __restrict__ mask,
                                  float* __restrict__ out) {
    int bt = blockIdx.x;
    const float4* xp4 = (const float4*)(x + (size_t)bt * NTOK * D);
    const float* mp = mask + (size_t)bt * NTOK;
    __shared__ float sm[NTOK];
    __shared__ float s_den;
    int tid = threadIdx.x;
    if (tid == 0) out[FMASK_OFF + bt] = 0.f;
    for (int i = tid; i < NTOK; i += 192) sm[i] = mp[i];
    __syncthreads();
    if (tid == 0) {
        float s = 0.f;
        for (int n = 0; n < NTOK; n++) s += sm[n];
        s_den = fmaxf(s, 1e-6f);
    }
    __syncthreads();
    float inv = 1.0f / s_den;
    float ax = 0.f, ay = 0.f, az = 0.f, aw = 0.f;
#pragma unroll 4
    for (int n = 0; n < NTOK; n++) {
        float m = sm[n];
        float4 v = xp4[n * 192 + tid];
        ax += v.x * m; ay += v.y * m; az += v.z * m; aw += v.w * m;
    }
    float4* fr = (float4*)(g_frame_repr + (size_t)bt * D);
    fr[tid] = make_float4(ax * inv, ay * inv, az * inv, aw * inv);
}

// ================= K2: frame-gram partials (24-way k-split) =================
__global__ __launch_bounds__(256, 1) void gf_partial_kernel() {
    int ks = blockIdx.x, b = blockIdx.y;
    const float* R = g_frame_repr + (size_t)b * T * D;
    __shared__ float As[128 * 18];
    int tid = threadIdx.x;
    int ti = tid & 15, tj = tid >> 4;

    ull acc[64];
#pragma unroll
    for (int i = 0; i < 64; i++) acc[i] = 0ull;

    for (int c = 0; c < 2; c++) {
        int k0 = ks * 32 + c * 16;
        __syncthreads();
#pragma unroll
        for (int r = 0; r < 8; r++) {
            int idx = tid + 256 * r;
            int row = idx >> 4, col = idx & 15;
            As[row * 18 + col] = R[(size_t)row * D + k0 + col];
        }
        __syncthreads();
#pragma unroll
        for (int kk = 0; kk < 16; kk += 2) {
            ull a2[8], b2[8];
#pragma unroll
            for (int u = 0; u < 8; u++)
                a2[u] = *(const ull*)&As[(ti + 16 * u) * 18 + kk];
#pragma unroll
            for (int v = 0; v < 8; v++)
                b2[v] = *(const ull*)&As[(tj + 16 * v) * 18 + kk];
#pragma unroll
            for (int u = 0; u < 8; u++)
#pragma unroll
                for (int v = 0; v < 8; v++)
                    asm("fma.rn.f32x2 %0, %1, %2, %0;"
                        : "+l"(acc[u * 8 + v]) : "l"(a2[u]), "l"(b2[v]));
        }
    }
    float* P = g_GFp[ks] + (size_t)b * 128 * 128;
#pragma unroll
    for (int u = 0; u < 8; u++) {
        int gi = ti + 16 * u;
#pragma unroll
        for (int v = 0; v < 8; v++) {
            int gj = tj + 16 * v;
            ull a = acc[u * 8 + v];
            float lo = __uint_as_float((unsigned)(a & 0xffffffffull));
            float hi = __uint_as_float((unsigned)(a >> 32));
            P[gi * 128 + gj] = lo + hi;
        }
    }
}

// ================= K3: novelty + frame FPS (per batch) =================
__global__ void novelty_fps_kernel(float* __restrict__ out) {
    extern __shared__ float s_GF[];        // 128*128 floats
    int b = blockIdx.x, tid = threadIdx.x; // 128 threads

    float4* dst4 = (float4*)s_GF;
    for (int i = tid; i < 128 * 128 / 4; i += 128) {
        float4 a = ((const float4*)(g_GFp[0] + (size_t)b * 16384))[i];
#pragma unroll
        for (int p = 1; p < 24; p++) {
            float4 v = ((const float4*)(g_GFp[p] + (size_t)b * 16384))[i];
            a.x += v.x; a.y += v.y; a.z += v.z; a.w += v.w;
        }
        dst4[i] = a;
    }
    __syncthreads();
    if (tid >= 32) return;
    int lane = tid;

    float c[4];
#pragma unroll
    for (int r = 0; r < 4; r++) c[r] = s_GF[lane + 32 * r];
    float s = s_GF[0];
    float bestv = -3e38f; int besti = 0;
#pragma unroll
    for (int t = 0; t < T; t++) {
        int r = t >> 5, t2 = t & 31;
        float ct = __shfl_sync(0xffffffffu, c[r], t2);
        float gtt = s_GF[t * 128 + t];
        float nv = gtt - 2.f * ct + s;
        if (nv > bestv) { bestv = nv; besti = t; }
#pragma unroll
        for (int rr = 0; rr < 4; rr++)
            c[rr] = 0.9f * c[rr] + 0.1f * s_GF[t * 128 + lane + 32 * rr];
        s = 0.81f * s + 0.18f * ct + 0.01f * gtt;
    }

    int last = besti;
    if (lane == 0) {
        g_frame_idx[b * KF] = last;
        out[FIDX_OFF + b * KF] = (float)last;
        out[FMASK_OFF + b * T + last] = 1.0f;
    }

    float n[4], md[4];
#pragma unroll
    for (int r = 0; r < 4; r++) {
        int i = lane + 32 * r;
        n[r] = s_GF[i * 128 + i];
        md[r] = __int_as_float(0x7f800000);
    }
    for (int step = 1; step < KF; step++) {
        float nl = s_GF[last * 128 + last];
        float bv = -3e38f; int bi = 0x7fffffff;
#pragma unroll
        for (int r = 0; r < 4; r++) {
            int i = lane + 32 * r;
            float d = n[r] + nl - 2.f * s_GF[last * 128 + i];
            md[r] = fminf(md[r], d);
            if (i == last) md[r] = -1.f;
            if (md[r] > bv) { bv = md[r]; bi = i; }
        }
        warp_argmax(bv, bi);
        last = bi;
        if (lane == 0) {
            g_frame_idx[b * KF + step] = last;
            out[FIDX_OFF + b * KF + step] = (float)last;
            out[FMASK_OFF + b * T + last] = 1.0f;
        }
    }
}

// ================= K4: token Gram via HMMA bf16-split =================
// grid (3 sym tiles, 64 frames), 256 threads (8 warps).
// Tile 128x128, pad NTOK->256. G = Hh*Hh^T + Hh*Hl^T + Hl*Hh^T.
// smem: 2 stages x {A,B} x {hi,lo} x 128 rows x 40 bf16 (pitch 80B, ldsm conflict-free)
#define GPITCH 40
#define GTILE  (128 * GPITCH)                 // bf16 elems per tile
#define GSMEM_BYTES (8 * GTILE * 2)           // 81920

__global__ __launch_bounds__(256, 1) void gram_hmma_kernel(const float* __restrict__ x,
                                                           float* __restrict__ out) {
    extern __shared__ __nv_bfloat16 sB[];
    uint32_t sb = smem_u32(sB);
    int tid = threadIdx.x;
    int w = tid >> 5, lane = tid & 31;
    int qp = blockIdx.x, f = blockIdx.y;
    int qi = qp >> 1, qj = (qp + 1) >> 1;

    // fold: zero tmask region of out
    {
        int g0 = (f * 3 + qp) * 256 + tid;
        for (int i = g0; i < B * T * NTOK; i += 192 * 256) out[TMASK_OFF + i] = 0.f;
    }

    int b = f >> 4;
    int fidx = g_frame_idx[f];
    const float* F = x + ((size_t)(b * T + fidx)) * NTOK * D;

    // per-thread load mapping (8 iters per tile): idx -> (row, 2*c2)
    int lrow = lane & 15, half = lane >> 4;

    float acc[64];
#pragma unroll
    for (int i = 0; i < 64; i++) acc[i] = 0.f;

    // ---- helpers as lambdas ----
    auto load_chunk = [&](int k0, float2* va, float2* vb) {
#pragma unroll
        for (int i = 0; i < 8; i++) {
            int idx = tid + 256 * i;
            int row = idx >> 4, c2 = (idx & 15) * 2;
            int ga = qi * 128 + row;
            int gb = qj * 128 + row;
            va[i] = (ga < NTOK) ? *(const float2*)(F + (size_t)ga * D + k0 + c2)
                                : make_float2(0.f, 0.f);
            vb[i] = (gb < NTOK) ? *(const float2*)(F + (size_t)gb * D + k0 + c2)
                                : make_float2(0.f, 0.f);
        }
    };
    auto store_chunk = [&](int stage, const float2* va, const float2* vb) {
        uint32_t* sm32 = (uint32_t*)sB;
        int base = stage * 4 * GTILE;
#pragma unroll
        for (int i = 0; i < 8; i++) {
            int idx = tid + 256 * i;
            int row = idx >> 4, c2 = (idx & 15) * 2;
            int off = row * GPITCH + c2;
            // A tile
            {
                float2 v = va[i];
                __nv_bfloat16 hx = __float2bfloat16(v.x);
                __nv_bfloat16 hy = __float2bfloat16(v.y);
                __nv_bfloat16 lx = __float2bfloat16(v.x - __bfloat162float(hx));
                __nv_bfloat16 ly = __float2bfloat16(v.y - __bfloat162float(hy));
                sm32[(base + off) >> 1] =
                    ((uint32_t)__bfloat16_as_ushort(hy) << 16) | __bfloat16_as_ushort(hx);
                sm32[(base + GTILE + off) >> 1] =
                    ((uint32_t)__bfloat16_as_ushort(ly) << 16) | __bfloat16_as_ushort(lx);
            }
            // B tile
            {
                float2 v = vb[i];
                __nv_bfloat16 hx = __float2bfloat16(v.x);
                __nv_bfloat16 hy = __float2bfloat16(v.y);
                __nv_bfloat16 lx = __float2bfloat16(v.x - __bfloat162float(hx));
                __nv_bfloat16 ly = __float2bfloat16(v.y - __bfloat162float(hy));
                sm32[(base + 2 * GTILE + off) >> 1] =
                    ((uint32_t)__bfloat16_as_ushort(hy) << 16) | __bfloat16_as_ushort(hx);
                sm32[(base + 3 * GTILE + off) >> 1] =
                    ((uint32_t)__bfloat16_as_ushort(ly) << 16) | __bfloat16_as_ushort(lx);
            }
        }
    };

    // prologue
    {
        float2 va[8], vb[8];
        load_chunk(0, va, vb);
        store_chunk(0, va, vb);
    }
    __syncthreads();

    for (int c = 0; c < 24; c++) {
        int buf = c & 1;
        float2 va[8], vb[8];
        if (c + 1 < 24) load_chunk((c + 1) * 32, va, vb);

        int base = buf * 4 * GTILE;
        uint32_t aAddrH = sb + 2 * (base + (w * 16 + lrow) * GPITCH + half * 8);
        uint32_t aAddrL = aAddrH + 2 * GTILE;
#pragma unroll
        for (int s = 0; s < 2; s++) {
            uint32_t ah[4], al[4];
            ldsm4(ah, aAddrH + 2 * (s * 16));
            ldsm4(al, aAddrL + 2 * (s * 16));
#pragma unroll
            for (int g = 0; g < 8; g++) {
                uint32_t bAddrH = sb + 2 * (base + 2 * GTILE +
                                 (g * 16 + lrow) * GPITCH + s * 16 + half * 8);
                uint32_t bh[4], bl[4];
                ldsm4(bh, bAddrH);
                ldsm4(bl, bAddrH + 2 * GTILE);
                float* d0 = acc + (2 * g) * 4;
                float* d1 = acc + (2 * g + 1) * 4;
                mma16816(d0, ah, bh[0], bh[2]);
                mma16816(d1, ah, bh[1], bh[3]);
                mma16816(d0, ah, bl[0], bl[2]);
                mma16816(d1, ah, bl[1], bl[3]);
                mma16816(d0, al, bh[0], bh[2]);
                mma16816(d1, al, bh[1], bh[3]);
            }
        }
        if (c + 1 < 24) store_chunk(buf ^ 1, va, vb);
        __syncthreads();
    }

    // epilogue: write C (and mirror for qp==1)
    int gid = lane >> 2, tig = lane & 3;
    float* G = g_G + (size_t)f * NTOK * NTOK;
    int gi0 = qi * 128 + w * 16 + gid;
    int gi1 = gi0 + 8;
#pragma unroll
    for (int j = 0; j < 16; j++) {
        int gj = qj * 128 + j * 8 + 2 * tig;
        if (gj < NTOK) {
            float c0 = acc[j * 4 + 0], c1 = acc[j * 4 + 1];
            float c2 = acc[j * 4 + 2], c3 = acc[j * 4 + 3];
            if (gi0 < NTOK) *(float2*)&G[(size_t)gi0 * NTOK + gj] = make_float2(c0, c1);
            if (gi1 < NTOK) *(float2*)&G[(size_t)gi1 * NTOK + gj] = make_float2(c2, c3);
            if (qp == 1) {
                if (gi0 < NTOK) {
                    G[(size_t)gj * NTOK + gi0] = c0;
                    G[(size_t)(gj + 1) * NTOK + gi0] = c1;
                }
                if (gi1 < NTOK) {
                    G[(size_t)gj * NTOK + gi1] = c2;
                    G[(size_t)(gj + 1) * NTOK + gi1] = c3;
                }
            }
        }
    }
}

// ================= K5: token FPS (per selected frame) =================
#define GPAD 197
__global__ void token_fps_kernel(float* __restrict__ out) {
    extern __shared__ float Gs[];            // NTOK*GPAD floats
    __shared__ float s_rs[NTOK];

    int f = blockIdx.x, tid = threadIdx.x;   // 224 threads
    const float* Gp = g_G + (size_t)f * NTOK * NTOK;
    if (tid < NTOK) {
        for (int i = 0; i < NTOK; i++)
            Gs[i * GPAD + tid] = Gp[(size_t)i * NTOK + tid];
    }
    __syncthreads();
    if (tid < NTOK) {
        const float* row = &Gs[tid * GPAD];
        float r0 = 0.f, r1 = 0.f, r2 = 0.f, r3 = 0.f;
#pragma unroll 4
        for (int j = 0; j < NTOK; j += 4) {
            r0 += row[j]; r1 += row[j + 1]; r2 += row[j + 2]; r3 += row[j + 3];
        }
        s_rs[tid] = (r0 + r1) + (r2 + r3);
    }
    __syncthreads();
    if (tid >= 32) return;
    int lane = tid;
    int fidx = g_frame_idx[f];
    int bb = f >> 4;
    size_t tmask_base = TMASK_OFF + ((size_t)(bb * T + fidx)) * NTOK;

    float n[7], md[7];
    float bv = -3e38f; int bi = 0x7fffffff;
#pragma unroll
    for (int q = 0; q < 7; q++) {
        int i = lane + 32 * q;
        bool val = i < NTOK;
        n[q]  = val ? Gs[i * GPAD + i] : 0.f;
        md[q] = val ? __int_as_float(0x7f800000) : -3e38f;
        float v = val ? (n[q] - s_rs[i] * (2.0f / 196.0f)) : -3e38f;
        if (v > bv) { bv = v; bi = i; }
    }
    warp_argmax(bv, bi);
    int last = bi;
    if (lane == 0) {
        g_token_idx[f * KT] = last;
        out[TIDX_OFF + f * KT] = (float)last;
        out[tmask_base + last] = 1.0f;
    }

    for (int s = 1; s < KT; s++) {
        float nl = Gs[last * GPAD + last];
        bv = -3e38f; bi = 0x7fffffff;
#pragma unroll
        for (int q = 0; q < 7; q++) {
            int i = lane + 32 * q;
            bool val = i < NTOK;
            float g = val ? Gs[last * GPAD + i] : 0.f;
            float d = n[q] + nl - 2.f * g;
            md[q] = fminf(md[q], d);
            if (i == last) md[q] = -1.f;
            float mv = val ? md[q] : -3e38f;
            if (mv > bv) { bv = mv; bi = i; }
        }
        warp_argmax(bv, bi);
        last = bi;
        if (lane == 0) {
            g_token_idx[f * KT + s] = last;
            out[TIDX_OFF + f * KT + s] = (float)last;
            out[tmask_base + last] = 1.0f;
        }
    }
}

// ================= K6: gather z =================
__global__ void gather_kernel(const float* __restrict__ x, float* __restrict__ out) {
    int row = blockIdx.x;
    int bk = row / KT;
    int t2 = row - bk * KT;
    int b = bk >> 4;
    int fidx = g_frame_idx[bk];
    int tok = g_token_idx[bk * KT + t2];
    const float4* src = (const float4*)(x + (((size_t)(b * T + fidx)) * NTOK + tok) * D);
    float4* dst = (float4*)(out + (size_t)row * D);
    dst[threadIdx.x] = src[threadIdx.x];
}

extern "C" void kernel_launch(void* const* d_in, const int* in_sizes, int n_in,
                              void* d_out, int out_size) {
    const float* x    = (const float*)d_in[0];
    const float* mask = (const float*)d_in[1];
    float* out = (float*)d_out;

    frame_repr_kernel<<<B * T, 192>>>(x, mask, out);           // 1
    gf_partial_kernel<<<dim3(24, B), 256>>>();                 // 2

    cudaFuncSetAttribute(novelty_fps_kernel,
                         cudaFuncAttributeMaxDynamicSharedMemorySize, 128 * 128 * 4);
    novelty_fps_kernel<<<B, 128, 128 * 128 * 4>>>(out);        // 3

    cudaFuncSetAttribute(gram_hmma_kernel,
                         cudaFuncAttributeMaxDynamicSharedMemorySize, GSMEM_BYTES);
    gram_hmma_kernel<<<dim3(3, NF), 256, GSMEM_BYTES>>>(x, out); // 4 (ncu slot)

    size_t dyn = (size_t)NTOK * GPAD * sizeof(float);
    cudaFuncSetAttribute(token_fps_kernel,
                         cudaFuncAttributeMaxDynamicSharedMemorySize, (int)dyn);
    token_fps_kernel<<<NF, 224, dyn>>>(out);                   // 5

    gather_kernel<<<B * KF * KT, 192>>>(x, out);               // 6
}